// round 8
// baseline (speedup 1.0000x reference)
#include <cuda_runtime.h>
#include <cuda_bf16.h>

#define N_USERS 100000
#define N_ITEMS 50000
#define N_NODES (N_USERS + N_ITEMS)
#define D 64
#define F 768
#define N_EDGES 4800000
#define BATCH 4096
#define LN_EPS 1e-5f

#define SCAN_CHUNK 1024
#define NSCAN ((N_NODES + SCAN_CHUNK - 1) / SCAN_CHUNK)   // 147

#define N_EDGE4 (N_EDGES / 4)                             // 1200000
#define GEMM_BLOCKS ((N_ITEMS + 63) / 64)                 // 782
#define GEMM_A 250
#define GEMM_B (GEMM_BLOCKS - GEMM_A)                     // 532
#define HIST4_BLOCKS ((N_EDGE4 + 255) / 256)              // 4688 (ceil!)
#define FILL4_BLOCKS ((N_EDGE4 + 255) / 256)              // 4688 (ceil!)
#define INIT_BLOCKS 1024
#define COMBO_A_BLOCKS (HIST4_BLOCKS + GEMM_A + INIT_BLOCKS)
#define COMBO_B_BLOCKS (FILL4_BLOCKS + GEMM_B)

#define GATHER_BLOCKS (3 * BATCH / 4)                     // 3072
#define LOSS_BLOCKS (N_ITEMS * D / 4 / 256)               // 3125 (exact)
#define OUT_BLOCKS (GATHER_BLOCKS + LOSS_BLOCKS)

// ---- scratch (device globals) ----
__device__ float g_e0[N_NODES * D];
__device__ float g_e1[N_NODES * D];
__device__ float g_e2[N_NODES * D];
__device__ float g_e3[N_NODES * D];
__device__ float g_ic[N_ITEMS * D];
__device__ int   g_deg[N_NODES];
__device__ int   g_off[N_NODES + 1];
__device__ int   g_cursor[N_NODES];
__device__ int   g_blksum[NSCAN];
__device__ int   g_blkoff[NSCAN];
__device__ int   g_csr_src[N_EDGES];
__device__ float g_csr_w[N_EDGES];
__device__ float g_partials[LOSS_BLOCKS];

// packed f32x2 FMA (sm_103a FFMA2 — exact fp32)
__device__ __forceinline__ unsigned long long pack2(float lo, float hi) {
    unsigned long long r;
    asm("mov.b64 %0, {%1, %2};" : "=l"(r) : "f"(lo), "f"(hi));
    return r;
}
__device__ __forceinline__ void ffma2(unsigned long long& a,
                                      unsigned long long c,
                                      unsigned long long b) {
    asm("fma.rn.f32x2 %0, %1, %2, %0;" : "+l"(a) : "l"(c), "l"(b));
}
__device__ __forceinline__ float2 unpack2(unsigned long long v) {
    float2 r;
    asm("mov.b64 {%0, %1}, %2;" : "=f"(r.x), "=f"(r.y) : "l"(v));
    return r;
}

// ---------------------------------------------------------------------------
// shared GEMM tile body (FFMA2): one 64-item x 64-dim tile
// ---------------------------------------------------------------------------
__device__ void gemm_tile(int tile,
                          const float* __restrict__ cf,
                          const float* __restrict__ Wp,
                          const float* __restrict__ bp,
                          const float* __restrict__ wg,
                          const float* __restrict__ bg,
                          const float* __restrict__ item_emb) {
    __shared__ float Cs[32][68];
    __shared__ float Ws[32][64];
    __shared__ float wgs[32];
    __shared__ float gates[64];

    const int tid   = threadIdx.x;
    const int d     = tid & 63;
    const int r     = tid >> 6;
    const int item0 = tile * 64;

    unsigned long long acc2[8];
#pragma unroll
    for (int i = 0; i < 8; i++) acc2[i] = 0ull;
    float gp = 0.f;

    for (int kt = 0; kt < F; kt += 32) {
#pragma unroll
        for (int j = 0; j < 8; j++) {
            int l = tid + j * 256;
            int it = l >> 5, k = l & 31;
            int item = item0 + it;
            Cs[k][it] = (item < N_ITEMS) ? cf[item * F + kt + k] : 0.f;
        }
#pragma unroll
        for (int j = 0; j < 8; j++) {
            int l = tid + j * 256;
            int k = l >> 6, dd = l & 63;
            Ws[k][dd] = Wp[(kt + k) * D + dd];
        }
        if (tid < 32) wgs[tid] = wg[kt + tid];
        __syncthreads();

        if (tid < 64) {
#pragma unroll
            for (int k = 0; k < 32; k++) gp += Cs[k][tid] * wgs[k];
        }
#pragma unroll
        for (int k = 0; k < 32; k++) {
            float wv = Ws[k][d];
            unsigned long long w2 = pack2(wv, wv);
            const ulonglong2* cp = (const ulonglong2*)&Cs[k][r * 16];
#pragma unroll
            for (int q = 0; q < 4; q++) {
                ulonglong2 c = cp[q];
                ffma2(acc2[q * 2 + 0], c.x, w2);
                ffma2(acc2[q * 2 + 1], c.y, w2);
            }
        }
        __syncthreads();
    }

    if (tid < 64) gates[tid] = 1.f / (1.f + expf(-(gp + bg[0])));
    __syncthreads();

    const float bpd = bp[d];
#pragma unroll
    for (int p = 0; p < 8; p++) {
        float2 a = unpack2(acc2[p]);
#pragma unroll
        for (int h = 0; h < 2; h++) {
            int it = p * 2 + h;
            int item = item0 + r * 16 + it;
            if (item < N_ITEMS) {
                float ic = (h ? a.y : a.x) + bpd;
                g_ic[item * D + d] = ic;
                float g = gates[r * 16 + it];
                g_e0[(N_USERS + item) * D + d] =
                    (1.f - g) * item_emb[item * D + d] + g * ic;
            }
        }
    }
}

// ---------------------------------------------------------------------------
__global__ void zero_deg_kernel() {
    int i = blockIdx.x * blockDim.x + threadIdx.x;
    if (i < N_NODES) g_deg[i] = 0;
}

// combo_A: hist (bounded!) || GEMM part 1 || user init
__global__ __launch_bounds__(256) void combo_a_kernel(
    const float* __restrict__ cf, const float* __restrict__ Wp,
    const float* __restrict__ bp, const float* __restrict__ wg,
    const float* __restrict__ bg, const float* __restrict__ item_emb,
    const float* __restrict__ user_emb, const int4* __restrict__ dst4) {
    const int bid = blockIdx.x;
    const int tid = threadIdx.x;
    if (bid < HIST4_BLOCKS) {
        int i = bid * 256 + tid;
        if (i < N_EDGE4) {
            int4 dd = dst4[i];
            atomicAdd(&g_deg[dd.x], 1);
            atomicAdd(&g_deg[dd.y], 1);
            atomicAdd(&g_deg[dd.z], 1);
            atomicAdd(&g_deg[dd.w], 1);
        }
        return;
    }
    int b2 = bid - HIST4_BLOCKS;
    if (b2 < GEMM_A) {
        gemm_tile(b2, cf, Wp, bp, wg, bg, item_emb);
        return;
    }
    int b3 = b2 - GEMM_A;
    const int n = N_USERS * D / 4;
    const float4* u4 = (const float4*)user_emb;
    float4* e4 = (float4*)g_e0;
    for (int i = b3 * 256 + tid; i < n; i += INIT_BLOCKS * 256)
        e4[i] = u4[i];
}

// ---------------------------------------------------------------------------
// scans
// ---------------------------------------------------------------------------
__global__ __launch_bounds__(1024) void scan_sum_kernel() {
    __shared__ int sh[1024];
    int gid = blockIdx.x * SCAN_CHUNK + threadIdx.x;
    sh[threadIdx.x] = (gid < N_NODES) ? g_deg[gid] : 0;
    __syncthreads();
#pragma unroll
    for (int o = 512; o; o >>= 1) {
        if (threadIdx.x < o) sh[threadIdx.x] += sh[threadIdx.x + o];
        __syncthreads();
    }
    if (threadIdx.x == 0) g_blksum[blockIdx.x] = sh[0];
}

// parallel top-level exclusive scan of 147 block sums
__global__ __launch_bounds__(256) void scan_top_kernel() {
    __shared__ int sh[2][256];
    int t = threadIdx.x;
    int v = (t < NSCAN) ? g_blksum[t] : 0;
    sh[0][t] = v;
    __syncthreads();
    int cur = 0;
#pragma unroll
    for (int o = 1; o < 256; o <<= 1) {
        int y = sh[cur][t];
        if (t >= o) y += sh[cur][t - o];
        sh[1 - cur][t] = y;
        __syncthreads();
        cur = 1 - cur;
    }
    if (t < NSCAN) g_blkoff[t] = sh[cur][t] - v;   // exclusive
}

__global__ __launch_bounds__(1024) void scan_blocks_kernel() {
    __shared__ int sh[2][1024];
    int gid = blockIdx.x * SCAN_CHUNK + threadIdx.x;
    int v = (gid < N_NODES) ? g_deg[gid] : 0;
    sh[0][threadIdx.x] = v;
    __syncthreads();
    int cur = 0;
#pragma unroll
    for (int o = 1; o < 1024; o <<= 1) {
        int y = sh[cur][threadIdx.x];
        if ((int)threadIdx.x >= o) y += sh[cur][threadIdx.x - o];
        sh[1 - cur][threadIdx.x] = y;
        __syncthreads();
        cur = 1 - cur;
    }
    int inc = sh[cur][threadIdx.x];
    int base = g_blkoff[blockIdx.x];
    if (gid < N_NODES) {
        int exc = base + inc - v;
        g_off[gid] = exc;
        g_cursor[gid] = exc;
        if (gid == N_NODES - 1) g_off[N_NODES] = base + inc;
    }
}

// ---------------------------------------------------------------------------
// combo_B: CSR fill (bounded!) || GEMM part 2
// ---------------------------------------------------------------------------
__global__ __launch_bounds__(256) void combo_b_kernel(
    const float* __restrict__ cf, const float* __restrict__ Wp,
    const float* __restrict__ bp, const float* __restrict__ wg,
    const float* __restrict__ bg, const float* __restrict__ item_emb,
    const int4* __restrict__ src4, const int4* __restrict__ dst4,
    const float4* __restrict__ w4) {
    const int bid = blockIdx.x;
    const int tid = threadIdx.x;
    if (bid < FILL4_BLOCKS) {
        int i = bid * 256 + tid;
        if (i < N_EDGE4) {
            int4   s = src4[i];
            int4   dd = dst4[i];
            float4 w = w4[i];
            int p0 = atomicAdd(&g_cursor[dd.x], 1);
            g_csr_src[p0] = s.x; g_csr_w[p0] = w.x;
            int p1 = atomicAdd(&g_cursor[dd.y], 1);
            g_csr_src[p1] = s.y; g_csr_w[p1] = w.y;
            int p2 = atomicAdd(&g_cursor[dd.z], 1);
            g_csr_src[p2] = s.z; g_csr_w[p2] = w.z;
            int p3 = atomicAdd(&g_cursor[dd.w], 1);
            g_csr_src[p3] = s.w; g_csr_w[p3] = w.w;
        }
        return;
    }
    gemm_tile(GEMM_A + (bid - FILL4_BLOCKS), cf, Wp, bp, wg, bg, item_emb);
}

// ---------------------------------------------------------------------------
// fused layer: half-warp per node, float4 per lane
// ---------------------------------------------------------------------------
__global__ __launch_bounds__(256) void layer_kernel(int l) {
    const float4* ein;
    float4* eout;
    if (l == 0)      { ein = (const float4*)g_e0; eout = (float4*)g_e1; }
    else if (l == 1) { ein = (const float4*)g_e1; eout = (float4*)g_e2; }
    else             { ein = (const float4*)g_e2; eout = (float4*)g_e3; }

    int warp = threadIdx.x >> 5;
    int lane = threadIdx.x & 31;
    int half = lane >> 4;
    int l16  = lane & 15;
    int node = blockIdx.x * 16 + warp * 2 + half;
    if (node >= N_NODES) return;
    int beg = g_off[node];
    int end = g_off[node + 1];

    float ax = 0.f, ay = 0.f, az = 0.f, aw = 0.f;
    int i = beg;
    for (; i + 4 <= end; i += 4) {
        int s0 = g_csr_src[i + 0], s1 = g_csr_src[i + 1];
        int s2 = g_csr_src[i + 2], s3 = g_csr_src[i + 3];
        float4 x0 = ein[s0 * 16 + l16];
        float4 x1 = ein[s1 * 16 + l16];
        float4 x2 = ein[s2 * 16 + l16];
        float4 x3 = ein[s3 * 16 + l16];
        float w0 = g_csr_w[i + 0], w1 = g_csr_w[i + 1];
        float w2 = g_csr_w[i + 2], w3 = g_csr_w[i + 3];
        ax += w0 * x0.x; ay += w0 * x0.y; az += w0 * x0.z; aw += w0 * x0.w;
        ax += w1 * x1.x; ay += w1 * x1.y; az += w1 * x1.z; aw += w1 * x1.w;
        ax += w2 * x2.x; ay += w2 * x2.y; az += w2 * x2.z; aw += w2 * x2.w;
        ax += w3 * x3.x; ay += w3 * x3.y; az += w3 * x3.z; aw += w3 * x3.w;
    }
    for (; i < end; i++) {
        int s = g_csr_src[i];
        float wv = g_csr_w[i];
        float4 x = ein[s * 16 + l16];
        ax += wv * x.x; ay += wv * x.y; az += wv * x.z; aw += wv * x.w;
    }

    float s = ax + ay + az + aw;
#pragma unroll
    for (int o = 8; o; o >>= 1) s += __shfl_xor_sync(0xFFFFFFFFu, s, o);
    float m = s * (1.f / 64.f);
    float dx = ax - m, dy = ay - m, dz = az - m, dw = aw - m;
    float v = dx * dx + dy * dy + dz * dz + dw * dw;
#pragma unroll
    for (int o = 8; o; o >>= 1) v += __shfl_xor_sync(0xFFFFFFFFu, v, o);
    float rs = rsqrtf(v * (1.f / 64.f) + LN_EPS);

    float4 r = ein[node * 16 + l16];
    eout[node * 16 + l16] =
        make_float4(dx * rs + r.x, dy * rs + r.y, dz * rs + r.z, dw * rs + r.w);
}

// ---------------------------------------------------------------------------
// fused outputs: gather blocks + loss-partial blocks
// ---------------------------------------------------------------------------
__global__ __launch_bounds__(256) void out_combo_kernel(
    const int* __restrict__ u, const int* __restrict__ p,
    const int* __restrict__ n, float* __restrict__ out) {
    const int bid = blockIdx.x;
    const int tid = threadIdx.x;

    if (bid < GATHER_BLOCKS) {
        int row  = bid * 4 + (tid >> 6);
        int d    = tid & 63;
        int which = row >> 12;
        int b     = row & 4095;
        int idx;
        if (which == 0)      idx = u[b];
        else if (which == 1) idx = N_USERS + p[b];
        else                 idx = N_USERS + n[b];
        long long o = (long long)idx * D + d;
        out[(long long)row * D + d] =
            (g_e0[o] + g_e1[o] + g_e2[o] + g_e3[o]) * 0.25f;
        return;
    }

    __shared__ float sh[256];
    int lb = bid - GATHER_BLOCKS;
    int i = lb * 256 + tid;
    const float4* e0 = (const float4*)(g_e0 + (long long)N_USERS * D);
    const float4* e1 = (const float4*)(g_e1 + (long long)N_USERS * D);
    const float4* e2 = (const float4*)(g_e2 + (long long)N_USERS * D);
    const float4* e3 = (const float4*)(g_e3 + (long long)N_USERS * D);
    const float4* ic = (const float4*)g_ic;
    float4 a = e0[i], b = e1[i], c = e2[i], d4 = e3[i], f = ic[i];
    float dx = (a.x + b.x + c.x + d4.x) * 0.25f - f.x;
    float dy = (a.y + b.y + c.y + d4.y) * 0.25f - f.y;
    float dz = (a.z + b.z + c.z + d4.z) * 0.25f - f.z;
    float dw = (a.w + b.w + c.w + d4.w) * 0.25f - f.w;
    sh[tid] = dx * dx + dy * dy + dz * dz + dw * dw;
    __syncthreads();
#pragma unroll
    for (int o = 128; o; o >>= 1) {
        if (tid < o) sh[tid] += sh[tid + o];
        __syncthreads();
    }
    if (tid == 0) g_partials[lb] = sh[0];
}

__global__ __launch_bounds__(1024) void loss_final_kernel(float* __restrict__ out) {
    __shared__ float sh[1024];
    float s = 0.f;
    for (int i = threadIdx.x; i < LOSS_BLOCKS; i += 1024) s += g_partials[i];
    sh[threadIdx.x] = s;
    __syncthreads();
#pragma unroll
    for (int o = 512; o; o >>= 1) {
        if (threadIdx.x < o) sh[threadIdx.x] += sh[threadIdx.x + o];
        __syncthreads();
    }
    if (threadIdx.x == 0)
        out[3 * BATCH * D] = sh[0] * (0.1f / (float)(N_ITEMS * D));
}

// ---------------------------------------------------------------------------
extern "C" void kernel_launch(void* const* d_in, const int* in_sizes, int n_in,
                              void* d_out, int out_size) {
    const int*   users     = (const int*)  d_in[0];
    const int*   pos_items = (const int*)  d_in[1];
    const int*   neg_items = (const int*)  d_in[2];
    const int*   edge_src  = (const int*)  d_in[3];
    const int*   edge_dst  = (const int*)  d_in[4];
    const float* edge_w    = (const float*)d_in[5];
    const float* user_emb  = (const float*)d_in[6];
    const float* item_emb  = (const float*)d_in[7];
    const float* cf        = (const float*)d_in[8];
    const float* Wp        = (const float*)d_in[9];
    const float* bp        = (const float*)d_in[10];
    const float* wg        = (const float*)d_in[11];
    const float* bg        = (const float*)d_in[12];
    float* out = (float*)d_out;

    zero_deg_kernel<<<(N_NODES + 255) / 256, 256>>>();
    combo_a_kernel<<<COMBO_A_BLOCKS, 256>>>(cf, Wp, bp, wg, bg, item_emb,
                                            user_emb, (const int4*)edge_dst);
    scan_sum_kernel<<<NSCAN, 1024>>>();
    scan_top_kernel<<<1, 256>>>();
    scan_blocks_kernel<<<NSCAN, 1024>>>();
    combo_b_kernel<<<COMBO_B_BLOCKS, 256>>>(cf, Wp, bp, wg, bg, item_emb,
                                            (const int4*)edge_src,
                                            (const int4*)edge_dst,
                                            (const float4*)edge_w);

    const int ln_blocks = (N_NODES + 15) / 16;
    layer_kernel<<<ln_blocks, 256>>>(0);
    layer_kernel<<<ln_blocks, 256>>>(1);
    layer_kernel<<<ln_blocks, 256>>>(2);

    out_combo_kernel<<<OUT_BLOCKS, 256>>>(users, pos_items, neg_items, out);
    loss_final_kernel<<<1, 1024>>>(out);
}

// round 9
// speedup vs baseline: 1.2559x; 1.2559x over previous
#include <cuda_runtime.h>
#include <cuda_bf16.h>

#define N_USERS 100000
#define N_ITEMS 50000
#define N_NODES (N_USERS + N_ITEMS)
#define D 64
#define F 768
#define N_EDGES 4800000
#define BATCH 4096
#define LN_EPS 1e-5f

#define SCAN_CHUNK 1024
#define NSCAN ((N_NODES + SCAN_CHUNK - 1) / SCAN_CHUNK)   // 147

#define GEMM_BLOCKS ((N_ITEMS + 63) / 64)                 // 782
#define FILL_BLOCKS ((N_EDGES + 255) / 256)               // 18750
#define INIT_BLOCKS 1024
#define COMBO_BLOCKS (GEMM_BLOCKS + FILL_BLOCKS + INIT_BLOCKS)

#define GATHER_BLOCKS (3 * BATCH / 4)                     // 3072
#define LOSS_BLOCKS (N_ITEMS * D / 4 / 256)               // 3125 (exact: 3200000/1024)
#define OUT_BLOCKS (GATHER_BLOCKS + LOSS_BLOCKS)

// ---- scratch (device globals) ----
__device__ float g_e0[N_NODES * D];
__device__ float g_e1[N_NODES * D];
__device__ float g_e2[N_NODES * D];
__device__ float g_e3[N_NODES * D];
__device__ float g_ic[N_ITEMS * D];
__device__ int   g_deg[N_NODES];
__device__ int   g_off[N_NODES + 1];
__device__ int   g_cursor[N_NODES];
__device__ int   g_blksum[NSCAN];
__device__ int   g_blkoff[NSCAN];
__device__ int   g_csr_src[N_EDGES];
__device__ float g_csr_w[N_EDGES];
__device__ float g_partials[LOSS_BLOCKS];

// packed f32x2 FMA (sm_103a FFMA2 — exact fp32)
__device__ __forceinline__ unsigned long long pack2(float lo, float hi) {
    unsigned long long r;
    asm("mov.b64 %0, {%1, %2};" : "=l"(r) : "f"(lo), "f"(hi));
    return r;
}
__device__ __forceinline__ void ffma2(unsigned long long& a,
                                      unsigned long long c,
                                      unsigned long long b) {
    asm("fma.rn.f32x2 %0, %1, %2, %0;" : "+l"(a) : "l"(c), "l"(b));
}
__device__ __forceinline__ float2 unpack2(unsigned long long v) {
    float2 r;
    asm("mov.b64 {%0, %1}, %2;" : "=f"(r.x), "=f"(r.y) : "l"(v));
    return r;
}

// ---------------------------------------------------------------------------
// CSR build stage 1
// ---------------------------------------------------------------------------
__global__ void zero_deg_kernel() {
    int i = blockIdx.x * blockDim.x + threadIdx.x;
    if (i < N_NODES) g_deg[i] = 0;
}

__global__ void hist_kernel(const int4* __restrict__ dst4) {
    int i = blockIdx.x * blockDim.x + threadIdx.x;
    if (i < N_EDGES / 4) {
        int4 d = dst4[i];
        atomicAdd(&g_deg[d.x], 1);
        atomicAdd(&g_deg[d.y], 1);
        atomicAdd(&g_deg[d.z], 1);
        atomicAdd(&g_deg[d.w], 1);
    }
}

__global__ __launch_bounds__(1024) void scan_sum_kernel() {
    __shared__ int sh[1024];
    int gid = blockIdx.x * SCAN_CHUNK + threadIdx.x;
    sh[threadIdx.x] = (gid < N_NODES) ? g_deg[gid] : 0;
    __syncthreads();
#pragma unroll
    for (int o = 512; o; o >>= 1) {
        if (threadIdx.x < o) sh[threadIdx.x] += sh[threadIdx.x + o];
        __syncthreads();
    }
    if (threadIdx.x == 0) g_blksum[blockIdx.x] = sh[0];
}

// parallel top-level exclusive scan of 147 block sums (measured 4.6us)
__global__ __launch_bounds__(256) void scan_top_kernel() {
    __shared__ int sh[2][256];
    int t = threadIdx.x;
    int v = (t < NSCAN) ? g_blksum[t] : 0;
    sh[0][t] = v;
    __syncthreads();
    int cur = 0;
#pragma unroll
    for (int o = 1; o < 256; o <<= 1) {
        int y = sh[cur][t];
        if (t >= o) y += sh[cur][t - o];
        sh[1 - cur][t] = y;
        __syncthreads();
        cur = 1 - cur;
    }
    if (t < NSCAN) g_blkoff[t] = sh[cur][t] - v;   // exclusive
}

__global__ __launch_bounds__(1024) void scan_blocks_kernel() {
    __shared__ int sh[2][1024];
    int gid = blockIdx.x * SCAN_CHUNK + threadIdx.x;
    int v = (gid < N_NODES) ? g_deg[gid] : 0;
    sh[0][threadIdx.x] = v;
    __syncthreads();
    int cur = 0;
#pragma unroll
    for (int o = 1; o < 1024; o <<= 1) {
        int y = sh[cur][threadIdx.x];
        if ((int)threadIdx.x >= o) y += sh[cur][threadIdx.x - o];
        sh[1 - cur][threadIdx.x] = y;
        __syncthreads();
        cur = 1 - cur;
    }
    int inc = sh[cur][threadIdx.x];
    int base = g_blkoff[blockIdx.x];
    if (gid < N_NODES) {
        int exc = base + inc - v;
        g_off[gid] = exc;
        g_cursor[gid] = exc;
        if (gid == N_NODES - 1) g_off[N_NODES] = base + inc;
    }
}

// ---------------------------------------------------------------------------
// combo (R6 winner): GEMM (FFMA2, low blockIdx) || scalar CSR fill || user init
// ---------------------------------------------------------------------------
__global__ __launch_bounds__(256) void combo_kernel(
    const float* __restrict__ cf, const float* __restrict__ Wp,
    const float* __restrict__ bp, const float* __restrict__ wg,
    const float* __restrict__ bg, const float* __restrict__ item_emb,
    const float* __restrict__ user_emb,
    const int* __restrict__ src, const int* __restrict__ dst,
    const float* __restrict__ w) {

    __shared__ float Cs[32][68];
    __shared__ float Ws[32][64];
    __shared__ float wgs[32];
    __shared__ float gates[64];

    const int bid = blockIdx.x;
    const int tid = threadIdx.x;

    if (bid >= GEMM_BLOCKS) {
        int b2 = bid - GEMM_BLOCKS;
        if (b2 < FILL_BLOCKS) {
            int e = b2 * 256 + tid;
            if (e < N_EDGES) {
                int pos = atomicAdd(&g_cursor[dst[e]], 1);
                g_csr_src[pos] = src[e];
                g_csr_w[pos] = w[e];
            }
        } else {
            int b3 = b2 - FILL_BLOCKS;
            const int n = N_USERS * D / 4;
            const float4* u4 = (const float4*)user_emb;
            float4* e4 = (float4*)g_e0;
            for (int i = b3 * 256 + tid; i < n; i += INIT_BLOCKS * 256)
                e4[i] = u4[i];
        }
        return;
    }

    // ---- fused item GEMM (FFMA2) + gate + mix ----
    const int d     = tid & 63;
    const int r     = tid >> 6;
    const int item0 = bid * 64;

    unsigned long long acc2[8];
#pragma unroll
    for (int i = 0; i < 8; i++) acc2[i] = 0ull;
    float gp = 0.f;

    for (int kt = 0; kt < F; kt += 32) {
#pragma unroll
        for (int j = 0; j < 8; j++) {
            int l = tid + j * 256;
            int it = l >> 5, k = l & 31;
            int item = item0 + it;
            Cs[k][it] = (item < N_ITEMS) ? cf[item * F + kt + k] : 0.f;
        }
#pragma unroll
        for (int j = 0; j < 8; j++) {
            int l = tid + j * 256;
            int k = l >> 6, dd = l & 63;
            Ws[k][dd] = Wp[(kt + k) * D + dd];
        }
        if (tid < 32) wgs[tid] = wg[kt + tid];
        __syncthreads();

        if (tid < 64) {
#pragma unroll
            for (int k = 0; k < 32; k++) gp += Cs[k][tid] * wgs[k];
        }
#pragma unroll
        for (int k = 0; k < 32; k++) {
            float wv = Ws[k][d];
            unsigned long long w2 = pack2(wv, wv);
            const ulonglong2* cp = (const ulonglong2*)&Cs[k][r * 16];
#pragma unroll
            for (int q = 0; q < 4; q++) {
                ulonglong2 c = cp[q];
                ffma2(acc2[q * 2 + 0], c.x, w2);
                ffma2(acc2[q * 2 + 1], c.y, w2);
            }
        }
        __syncthreads();
    }

    if (tid < 64) gates[tid] = 1.f / (1.f + expf(-(gp + bg[0])));
    __syncthreads();

    const float bpd = bp[d];
#pragma unroll
    for (int p = 0; p < 8; p++) {
        float2 a = unpack2(acc2[p]);
#pragma unroll
        for (int h = 0; h < 2; h++) {
            int it = p * 2 + h;
            int item = item0 + r * 16 + it;
            if (item < N_ITEMS) {
                float ic = (h ? a.y : a.x) + bpd;
                g_ic[item * D + d] = ic;
                float g = gates[r * 16 + it];
                g_e0[(N_USERS + item) * D + d] =
                    (1.f - g) * item_emb[item * D + d] + g * ic;
            }
        }
    }
}

// ---------------------------------------------------------------------------
// fused layer: half-warp per node, float4 per lane
// ---------------------------------------------------------------------------
__global__ __launch_bounds__(256) void layer_kernel(int l) {
    const float4* ein;
    float4* eout;
    if (l == 0)      { ein = (const float4*)g_e0; eout = (float4*)g_e1; }
    else if (l == 1) { ein = (const float4*)g_e1; eout = (float4*)g_e2; }
    else             { ein = (const float4*)g_e2; eout = (float4*)g_e3; }

    int warp = threadIdx.x >> 5;
    int lane = threadIdx.x & 31;
    int half = lane >> 4;
    int l16  = lane & 15;
    int node = blockIdx.x * 16 + warp * 2 + half;
    if (node >= N_NODES) return;
    int beg = g_off[node];
    int end = g_off[node + 1];

    float ax = 0.f, ay = 0.f, az = 0.f, aw = 0.f;
    int i = beg;
    for (; i + 4 <= end; i += 4) {
        int s0 = g_csr_src[i + 0], s1 = g_csr_src[i + 1];
        int s2 = g_csr_src[i + 2], s3 = g_csr_src[i + 3];
        float4 x0 = ein[s0 * 16 + l16];
        float4 x1 = ein[s1 * 16 + l16];
        float4 x2 = ein[s2 * 16 + l16];
        float4 x3 = ein[s3 * 16 + l16];
        float w0 = g_csr_w[i + 0], w1 = g_csr_w[i + 1];
        float w2 = g_csr_w[i + 2], w3 = g_csr_w[i + 3];
        ax += w0 * x0.x; ay += w0 * x0.y; az += w0 * x0.z; aw += w0 * x0.w;
        ax += w1 * x1.x; ay += w1 * x1.y; az += w1 * x1.z; aw += w1 * x1.w;
        ax += w2 * x2.x; ay += w2 * x2.y; az += w2 * x2.z; aw += w2 * x2.w;
        ax += w3 * x3.x; ay += w3 * x3.y; az += w3 * x3.z; aw += w3 * x3.w;
    }
    for (; i < end; i++) {
        int s = g_csr_src[i];
        float wv = g_csr_w[i];
        float4 x = ein[s * 16 + l16];
        ax += wv * x.x; ay += wv * x.y; az += wv * x.z; aw += wv * x.w;
    }

    float s = ax + ay + az + aw;
#pragma unroll
    for (int o = 8; o; o >>= 1) s += __shfl_xor_sync(0xFFFFFFFFu, s, o);
    float m = s * (1.f / 64.f);
    float dx = ax - m, dy = ay - m, dz = az - m, dw = aw - m;
    float v = dx * dx + dy * dy + dz * dz + dw * dw;
#pragma unroll
    for (int o = 8; o; o >>= 1) v += __shfl_xor_sync(0xFFFFFFFFu, v, o);
    float rs = rsqrtf(v * (1.f / 64.f) + LN_EPS);

    float4 r = ein[node * 16 + l16];
    eout[node * 16 + l16] =
        make_float4(dx * rs + r.x, dy * rs + r.y, dz * rs + r.z, dw * rs + r.w);
}

// ---------------------------------------------------------------------------
// fused outputs: gather blocks + loss-partial blocks (measured-safe in R8)
// ---------------------------------------------------------------------------
__global__ __launch_bounds__(256) void out_combo_kernel(
    const int* __restrict__ u, const int* __restrict__ p,
    const int* __restrict__ n, float* __restrict__ out) {
    const int bid = blockIdx.x;
    const int tid = threadIdx.x;

    if (bid < GATHER_BLOCKS) {
        int row  = bid * 4 + (tid >> 6);
        int d    = tid & 63;
        int which = row >> 12;
        int b     = row & 4095;
        int idx;
        if (which == 0)      idx = u[b];
        else if (which == 1) idx = N_USERS + p[b];
        else                 idx = N_USERS + n[b];
        long long o = (long long)idx * D + d;
        out[(long long)row * D + d] =
            (g_e0[o] + g_e1[o] + g_e2[o] + g_e3[o]) * 0.25f;
        return;
    }

    __shared__ float sh[256];
    int lb = bid - GATHER_BLOCKS;
    int i = lb * 256 + tid;
    const float4* e0 = (const float4*)(g_e0 + (long long)N_USERS * D);
    const float4* e1 = (const float4*)(g_e1 + (long long)N_USERS * D);
    const float4* e2 = (const float4*)(g_e2 + (long long)N_USERS * D);
    const float4* e3 = (const float4*)(g_e3 + (long long)N_USERS * D);
    const float4* ic = (const float4*)g_ic;
    float4 a = e0[i], b = e1[i], c = e2[i], d4 = e3[i], f = ic[i];
    float dx = (a.x + b.x + c.x + d4.x) * 0.25f - f.x;
    float dy = (a.y + b.y + c.y + d4.y) * 0.25f - f.y;
    float dz = (a.z + b.z + c.z + d4.z) * 0.25f - f.z;
    float dw = (a.w + b.w + c.w + d4.w) * 0.25f - f.w;
    sh[tid] = dx * dx + dy * dy + dz * dz + dw * dw;
    __syncthreads();
#pragma unroll
    for (int o = 128; o; o >>= 1) {
        if (tid < o) sh[tid] += sh[tid + o];
        __syncthreads();
    }
    if (tid == 0) g_partials[lb] = sh[0];
}

__global__ __launch_bounds__(1024) void loss_final_kernel(float* __restrict__ out) {
    __shared__ float sh[1024];
    float s = 0.f;
    for (int i = threadIdx.x; i < LOSS_BLOCKS; i += 1024) s += g_partials[i];
    sh[threadIdx.x] = s;
    __syncthreads();
#pragma unroll
    for (int o = 512; o; o >>= 1) {
        if (threadIdx.x < o) sh[threadIdx.x] += sh[threadIdx.x + o];
        __syncthreads();
    }
    if (threadIdx.x == 0)
        out[3 * BATCH * D] = sh[0] * (0.1f / (float)(N_ITEMS * D));
}

// ---------------------------------------------------------------------------
extern "C" void kernel_launch(void* const* d_in, const int* in_sizes, int n_in,
                              void* d_out, int out_size) {
    const int*   users     = (const int*)  d_in[0];
    const int*   pos_items = (const int*)  d_in[1];
    const int*   neg_items = (const int*)  d_in[2];
    const int*   edge_src  = (const int*)  d_in[3];
    const int*   edge_dst  = (const int*)  d_in[4];
    const float* edge_w    = (const float*)d_in[5];
    const float* user_emb  = (const float*)d_in[6];
    const float* item_emb  = (const float*)d_in[7];
    const float* cf        = (const float*)d_in[8];
    const float* Wp        = (const float*)d_in[9];
    const float* bp        = (const float*)d_in[10];
    const float* wg        = (const float*)d_in[11];
    const float* bg        = (const float*)d_in[12];
    float* out = (float*)d_out;

    zero_deg_kernel<<<(N_NODES + 255) / 256, 256>>>();
    hist_kernel<<<(N_EDGES / 4 + 255) / 256, 256>>>((const int4*)edge_dst);
    scan_sum_kernel<<<NSCAN, 1024>>>();
    scan_top_kernel<<<1, 256>>>();
    scan_blocks_kernel<<<NSCAN, 1024>>>();

    combo_kernel<<<COMBO_BLOCKS, 256>>>(cf, Wp, bp, wg, bg, item_emb,
                                        user_emb, edge_src, edge_dst, edge_w);

    const int ln_blocks = (N_NODES + 15) / 16;
    layer_kernel<<<ln_blocks, 256>>>(0);
    layer_kernel<<<ln_blocks, 256>>>(1);
    layer_kernel<<<ln_blocks, 256>>>(2);

    out_combo_kernel<<<OUT_BLOCKS, 256>>>(users, pos_items, neg_items, out);
    loss_final_kernel<<<1, 1024>>>(out);
}